// round 11
// baseline (speedup 1.0000x reference)
#include <cuda_runtime.h>
#include <cuda_bf16.h>
#include <cstdint>

// InterAgg (FRAUDRE inter-relation aggregation), GB300 sm_103a.
//
// out[n] = [ self | relu(self) | sum_r relu(mean_j feat[nidx_r[n,j]]) * softmax(alpha)[64:,r] ]
// (softmax rows sum to 1 => aggregated first half == relu(self) exactly)
//
// R10: corrected L2-residency experiment.
//  - rows < KEEP_ROWS: ld.global.nc.L2::evict_last.v8.b32 (pinned ~82MB across
//    graph replays; v8 width is a ptxas requirement for evict hints on sm_103a)
//  - all other rows: PLAIN ld.global.nc.v8.b32 (default policy keeps the
//    intra-iteration duplicate-touch reuse that evict_first destroyed in R9)
//  - no `volatile` on the loads (R9's volatile serialized issue, MLP collapse)
//  - output written with st.global.cs (streaming; never read back)
// Warp layout: group g=lane>>3 covers row j+g, sublane sl=lane&7 owns dims
// 8sl..8sl+7; one warp instruction gathers 4 rows (1024B coalesced).

#define NB 8192
#define DEG 32
#define KEEP_ROWS 320000   // 320000 rows * 256B = 81.9 MB pinned set

__device__ __forceinline__ void ldg_keep8(const float* p, int keep, float* v) {
    uint32_t r0, r1, r2, r3, r4, r5, r6, r7;
    asm("{\n\t"
        ".reg .pred pk;\n\t"
        "setp.ne.u32 pk, %9, 0;\n\t"
        "@pk  ld.global.nc.L2::evict_last.v8.b32 {%0,%1,%2,%3,%4,%5,%6,%7}, [%8];\n\t"
        "@!pk ld.global.nc.v8.b32                {%0,%1,%2,%3,%4,%5,%6,%7}, [%8];\n\t"
        "}"
        : "=r"(r0), "=r"(r1), "=r"(r2), "=r"(r3),
          "=r"(r4), "=r"(r5), "=r"(r6), "=r"(r7)
        : "l"(p), "r"(keep));
    v[0] = __uint_as_float(r0); v[1] = __uint_as_float(r1);
    v[2] = __uint_as_float(r2); v[3] = __uint_as_float(r3);
    v[4] = __uint_as_float(r4); v[5] = __uint_as_float(r5);
    v[6] = __uint_as_float(r6); v[7] = __uint_as_float(r7);
}

__device__ __forceinline__ void stg_cs4(float* p, float a, float b, float c, float d) {
    asm volatile("st.global.cs.v4.f32 [%0], {%1,%2,%3,%4};"
                 :: "l"(p), "f"(a), "f"(b), "f"(c), "f"(d) : "memory");
}

__device__ __forceinline__ void softmax3(float& a, float& b, float& c) {
    float m = fmaxf(a, fmaxf(b, c));
    float e0 = __expf(a - m);
    float e1 = __expf(b - m);
    float e2 = __expf(c - m);
    float inv = __frcp_rn(e0 + e1 + e2);
    a = e0 * inv; b = e1 * inv; c = e2 * inv;
}

__global__ __launch_bounds__(256, 3)
void interagg_kernel(const float* __restrict__ feat,    // (NUM_NODES, 64)
                     const float* __restrict__ alpha,   // (128, 3)
                     const int*   __restrict__ nodes,   // (NB,)
                     const int*   __restrict__ n1,      // (NB, DEG)
                     const int*   __restrict__ n2,
                     const int*   __restrict__ n3,
                     float*       __restrict__ out)     // (NB, 192)
{
    const int w    = (blockIdx.x * blockDim.x + threadIdx.x) >> 5;
    const int lane = threadIdx.x & 31;
    if (w >= NB) return;

    const int g  = lane >> 3;   // row-group 0..3
    const int sl = lane & 7;    // owns dims 8sl..8sl+7
    const int fo = sl * 8;      // float offset within a feature row

    // --- index loads (coalesced; lane j owns neighbor j) ---
    const int node = __ldg(&nodes[w]);
    const int base = w * DEG + lane;
    const int i1 = __ldg(&n1[base]);
    const int i2 = __ldg(&n2[base]);
    const int i3 = __ldg(&n3[base]);

    // --- self row ---
    float s[8];
    ldg_keep8(feat + (size_t)node * 64 + fo, node < KEEP_ROWS, s);

    float a1[8] = {0,0,0,0,0,0,0,0};
    float a2[8] = {0,0,0,0,0,0,0,0};
    float a3[8] = {0,0,0,0,0,0,0,0};

    // --- gathers: one v8 warp instruction = 4 neighbor rows (1024B) ---
#pragma unroll
    for (int i = 0; i < DEG / 4; i++) {
        const int src = 4 * i + g;
        const int x1 = __shfl_sync(0xffffffffu, i1, src);
        const int x2 = __shfl_sync(0xffffffffu, i2, src);
        const int x3 = __shfl_sync(0xffffffffu, i3, src);

        float v1[8], v2[8], v3[8];
        ldg_keep8(feat + (size_t)x1 * 64 + fo, x1 < KEEP_ROWS, v1);
        ldg_keep8(feat + (size_t)x2 * 64 + fo, x2 < KEEP_ROWS, v2);
        ldg_keep8(feat + (size_t)x3 * 64 + fo, x3 < KEEP_ROWS, v3);

#pragma unroll
        for (int k = 0; k < 8; k++) {
            a1[k] += v1[k];
            a2[k] += v2[k];
            a3[k] += v3[k];
        }
    }

    // --- fold the 4 row-groups (lanes l, l^8, l^16, l^24 share dims) ---
#pragma unroll
    for (int k = 0; k < 8; k++) {
        a1[k] += __shfl_xor_sync(0xffffffffu, a1[k], 8);
        a2[k] += __shfl_xor_sync(0xffffffffu, a2[k], 8);
        a3[k] += __shfl_xor_sync(0xffffffffu, a3[k], 8);
        a1[k] += __shfl_xor_sync(0xffffffffu, a1[k], 16);
        a2[k] += __shfl_xor_sync(0xffffffffu, a2[k], 16);
        a3[k] += __shfl_xor_sync(0xffffffffu, a3[k], 16);
    }

    // --- softmax weights for agg dims 64+8sl .. 64+8sl+7 ---
    // alpha row r starts at float 3r; rows 64+8sl.. => floats 192+24sl..+23
    float wv[24];
    {
        const float4* ap = reinterpret_cast<const float4*>(alpha + 192 + 24 * sl);
#pragma unroll
        for (int q = 0; q < 6; q++) {
            float4 t = __ldg(&ap[q]);
            wv[4 * q + 0] = t.x; wv[4 * q + 1] = t.y;
            wv[4 * q + 2] = t.z; wv[4 * q + 3] = t.w;
        }
    }
    float o[8];
    const float inv = 1.0f / (float)DEG;
#pragma unroll
    for (int k = 0; k < 8; k++) {
        float w0 = wv[3 * k + 0], w1 = wv[3 * k + 1], w2 = wv[3 * k + 2];
        softmax3(w0, w1, w2);
        const float g1 = fmaxf(a1[k] * inv, 0.f);
        const float g2 = fmaxf(a2[k] * inv, 0.f);
        const float g3 = fmaxf(a3[k] * inv, 0.f);
        o[k] = g1 * w0 + g2 * w1 + g3 * w2;
    }

    // --- write 192 floats: [self | relu(self) | weighted agg], streaming ---
    float* ob = out + (size_t)w * 192;
    if (g == 0) {
        stg_cs4(ob + 8 * sl + 0, s[0], s[1], s[2], s[3]);
        stg_cs4(ob + 8 * sl + 4, s[4], s[5], s[6], s[7]);
    } else if (g == 1) {
        stg_cs4(ob + 64 + 8 * sl + 0, fmaxf(s[0], 0.f), fmaxf(s[1], 0.f),
                                      fmaxf(s[2], 0.f), fmaxf(s[3], 0.f));
        stg_cs4(ob + 64 + 8 * sl + 4, fmaxf(s[4], 0.f), fmaxf(s[5], 0.f),
                                      fmaxf(s[6], 0.f), fmaxf(s[7], 0.f));
    } else if (g == 2) {
        stg_cs4(ob + 128 + 8 * sl + 0, o[0], o[1], o[2], o[3]);
        stg_cs4(ob + 128 + 8 * sl + 4, o[4], o[5], o[6], o[7]);
    }
}

extern "C" void kernel_launch(void* const* d_in, const int* in_sizes, int n_in,
                              void* d_out, int out_size) {
    const float* feat  = (const float*)d_in[0];
    const float* alpha = (const float*)d_in[1];
    const int*   nodes = (const int*)d_in[2];
    const int*   n1    = (const int*)d_in[3];
    const int*   n2    = (const int*)d_in[4];
    const int*   n3    = (const int*)d_in[5];
    float*       out   = (float*)d_out;

    const int threads = 256;   // 8 warps = 8 nodes / block
    const int blocks  = (NB * 32 + threads - 1) / threads;  // 1024
    interagg_kernel<<<blocks, threads>>>(feat, alpha, nodes, n1, n2, n3, out);
}

// round 12
// speedup vs baseline: 2.7815x; 2.7815x over previous
#include <cuda_runtime.h>
#include <cuda_bf16.h>
#include <cstdint>

// InterAgg (FRAUDRE inter-relation aggregation), GB300 sm_103a.
//
// out[n] = [ self | relu(self) | sum_r relu(mean_j feat[nidx_r[n,j]]) * softmax(alpha)[64:,r] ]
// (softmax rows sum to 1 => aggregated first half == relu(self) exactly)
//
// R11: gathers via cp.async.bulk (UBLKCP bulk-DMA) into SMEM instead of LDG.
// Rationale: all LDG variants pin at 5.2TB/s with DRAM only ~66% busy =>
// bound by the per-SM L1tex in-flight line cap (~166 lines needed), not by
// DRAM. Bulk copies queue in the async/TMA engine with ~200KB outstanding
// per SM (8 CTAs x 25KB), bypassing that cap.
//
// One CTA (128 threads) per batch node:
//   warp 0 issues 97 x 256B bulk copies (self + 3x32 neighbor rows),
//   mbarrier expect_tx = 24832B, all warps wait,
//   warps 0-2 mean-reduce one relation each from SMEM,
//   warp 3 writes self | relu(self), then 64 threads combine with softmax3.

#define NB 8192
#define DEG 32

__device__ __forceinline__ uint32_t smem_u32(const void* p) {
    uint32_t a;
    asm("{ .reg .u64 t; cvta.to.shared.u64 t, %1; cvt.u32.u64 %0, t; }"
        : "=r"(a) : "l"(p));
    return a;
}

__device__ __forceinline__ void bulk_cp_row(uint32_t dst, const float* src, uint32_t mb) {
    asm volatile(
        "cp.async.bulk.shared::cluster.global.mbarrier::complete_tx::bytes "
        "[%0], [%1], 256, [%2];"
        :: "r"(dst), "l"(src), "r"(mb) : "memory");
}

__global__ __launch_bounds__(128, 8)
void interagg_kernel(const float* __restrict__ feat,    // (NUM_NODES, 64)
                     const float* __restrict__ alpha,   // (128, 3)
                     const int*   __restrict__ nodes,   // (NB,)
                     const int*   __restrict__ n1,      // (NB, DEG)
                     const int*   __restrict__ n2,
                     const int*   __restrict__ n3,
                     float*       __restrict__ out)     // (NB, 192)
{
    __shared__ __align__(16) float rows[97 * 64];      // 96 neighbor rows + self
    __shared__ float comb[3][64];
    __shared__ __align__(8) unsigned long long mbar;

    const int w    = blockIdx.x;
    const int tid  = threadIdx.x;
    const int wid  = tid >> 5;
    const int lane = tid & 31;
    const uint32_t mb = smem_u32(&mbar);

    if (tid == 0) {
        asm volatile("mbarrier.init.shared.b64 [%0], 1;" :: "r"(mb) : "memory");
        asm volatile("mbarrier.arrive.expect_tx.shared.b64 _, [%0], %1;"
                     :: "r"(mb), "r"(97 * 256) : "memory");
    }
    __syncthreads();

    // --- issue 97 bulk copies from warp 0 (3 per lane + self on lane 0) ---
    if (wid == 0) {
        const uint32_t dst = smem_u32(rows);
        const int b  = w * DEG + lane;
        const int i1 = n1[b];
        const int i2 = n2[b];
        const int i3 = n3[b];
        bulk_cp_row(dst + (uint32_t)(lane)       * 256, feat + (size_t)i1 * 64, mb);
        bulk_cp_row(dst + (uint32_t)(32 + lane)  * 256, feat + (size_t)i2 * 64, mb);
        bulk_cp_row(dst + (uint32_t)(64 + lane)  * 256, feat + (size_t)i3 * 64, mb);
        if (lane == 0) {
            const int nd = nodes[w];
            bulk_cp_row(dst + 96u * 256, feat + (size_t)nd * 64, mb);
        }
    }

    // --- wait for all 24832 bytes (phase 0; fresh barrier every launch) ---
    asm volatile(
        "{\n\t"
        ".reg .pred P;\n\t"
        "WAIT_%=:\n\t"
        "mbarrier.try_wait.parity.acquire.cta.shared::cta.b64 P, [%0], 0, 0x989680;\n\t"
        "@P bra.uni DONE_%=;\n\t"
        "bra.uni WAIT_%=;\n\t"
        "DONE_%=:\n\t"
        "}" :: "r"(mb) : "memory");

    if (wid < 3) {
        // warp r: mean over relation r's 32 rows; lane owns dims {2l,2l+1}
        const float2* rp = reinterpret_cast<const float2*>(rows) + wid * 32 * 32 + lane;
        float sx = 0.f, sy = 0.f;
#pragma unroll
        for (int j = 0; j < 32; j++) {
            const float2 v = rp[j * 32];
            sx += v.x; sy += v.y;
        }
        comb[wid][2 * lane]     = fmaxf(sx * (1.0f / 32.0f), 0.f);
        comb[wid][2 * lane + 1] = fmaxf(sy * (1.0f / 32.0f), 0.f);
    } else {
        // warp 3: self | relu(self)
        const float2* sp = reinterpret_cast<const float2*>(rows + 96 * 64);
        const float2 s = sp[lane];
        float2* ob = reinterpret_cast<float2*>(out + (size_t)w * 192);
        ob[lane]      = s;
        ob[32 + lane] = make_float2(fmaxf(s.x, 0.f), fmaxf(s.y, 0.f));
    }
    __syncthreads();

    // --- inter-relation combine with per-dim softmax over alpha[64+d] ---
    if (tid < 64) {
        const int d = tid;
        const float a0 = __ldg(&alpha[(64 + d) * 3 + 0]);
        const float a1 = __ldg(&alpha[(64 + d) * 3 + 1]);
        const float a2 = __ldg(&alpha[(64 + d) * 3 + 2]);
        const float m  = fmaxf(a0, fmaxf(a1, a2));
        const float e0 = __expf(a0 - m);
        const float e1 = __expf(a1 - m);
        const float e2 = __expf(a2 - m);
        const float inv = __frcp_rn(e0 + e1 + e2);
        out[(size_t)w * 192 + 128 + d] =
            (comb[0][d] * e0 + comb[1][d] * e1 + comb[2][d] * e2) * inv;
    }
}

extern "C" void kernel_launch(void* const* d_in, const int* in_sizes, int n_in,
                              void* d_out, int out_size) {
    const float* feat  = (const float*)d_in[0];
    const float* alpha = (const float*)d_in[1];
    const int*   nodes = (const int*)d_in[2];
    const int*   n1    = (const int*)d_in[3];
    const int*   n2    = (const int*)d_in[4];
    const int*   n3    = (const int*)d_in[5];
    float*       out   = (float*)d_out;

    interagg_kernel<<<NB, 128>>>(feat, alpha, nodes, n1, n2, n3, out);
}

// round 13
// speedup vs baseline: 3.6352x; 1.3069x over previous
#include <cuda_runtime.h>
#include <cuda_bf16.h>
#include <cstdint>

// InterAgg (FRAUDRE inter-relation aggregation), GB300 sm_103a.
//
// out[n] = [ self | relu(self) | sum_r relu(mean_j feat[nidx_r[n,j]]) * softmax(alpha)[64:,r] ]
// (softmax rows sum to 1 => aggregated first half == relu(self) exactly)
//
// R12: DUAL-ENGINE gather. LDG path (5.2TB/s cap, rel 1+2+self) and
// cp.async.bulk DMA path (4TB/s cap, rel 3 -> SMEM) run concurrently;
// their in-flight pools are separate, so combined demand (~7.8TB/s) can
// finally push DRAM (idle ~35% in every single-path variant) toward
// saturation. One warp per node; per-warp mbarrier + 8KB SMEM slice;
// no cross-warp synchronization at all.

#define NB 8192
#define DEG 32
#define ED 64
#define WPC 4   // warps (nodes) per CTA

__device__ __forceinline__ uint32_t smem_u32(const void* p) {
    uint32_t a;
    asm("{ .reg .u64 t; cvta.to.shared.u64 t, %1; cvt.u32.u64 %0, t; }"
        : "=r"(a) : "l"(p));
    return a;
}

__device__ __forceinline__ void bulk_cp_row(uint32_t dst, const float* src, uint32_t mb) {
    asm volatile(
        "cp.async.bulk.shared::cluster.global.mbarrier::complete_tx::bytes "
        "[%0], [%1], 256, [%2];"
        :: "r"(dst), "l"(src), "r"(mb) : "memory");
}

__device__ __forceinline__ void softmax3(float& a, float& b, float& c) {
    float m = fmaxf(a, fmaxf(b, c));
    float e0 = __expf(a - m);
    float e1 = __expf(b - m);
    float e2 = __expf(c - m);
    float inv = __frcp_rn(e0 + e1 + e2);
    a = e0 * inv; b = e1 * inv; c = e2 * inv;
}

__global__ __launch_bounds__(128, 4)
void interagg_kernel(const float*  __restrict__ feat,    // (NUM_NODES, 64)
                     const float2* __restrict__ feat2,   // same buffer as float2
                     const float*  __restrict__ alpha,   // (128, 3)
                     const int*    __restrict__ nodes,   // (NB,)
                     const int*    __restrict__ n1,      // (NB, DEG)
                     const int*    __restrict__ n2,
                     const int*    __restrict__ n3,
                     float*        __restrict__ out)     // (NB, 192)
{
    __shared__ __align__(128) float rows[WPC][DEG * 64];          // 8KB per warp
    __shared__ __align__(8)   unsigned long long mbar[WPC];

    const int wid  = threadIdx.x >> 5;
    const int lane = threadIdx.x & 31;
    const int w    = blockIdx.x * WPC + wid;

    const uint32_t mb = smem_u32(&mbar[wid]);

    // --- per-warp mbarrier init (fresh every launch; phase 0) ---
    if (lane == 0) {
        asm volatile("mbarrier.init.shared.b64 [%0], 1;" :: "r"(mb) : "memory");
        asm volatile("mbarrier.arrive.expect_tx.shared.b64 _, [%0], %1;"
                     :: "r"(mb), "r"(DEG * 256) : "memory");
    }
    __syncwarp();

    // --- relation 3: one bulk-DMA 256B row per lane, issued FIRST so the
    //     async engine works underneath the LDG loop below ---
    const int base = w * DEG + lane;
    const int i3 = __ldg(&n3[base]);
    bulk_cp_row(smem_u32(&rows[wid][0]) + (uint32_t)lane * 256,
                feat + (size_t)i3 * 64, mb);

    // --- relations 1,2 + self via LDG (proven 5.2TB/s path) ---
    const int node = __ldg(&nodes[w]);
    const int i1 = __ldg(&n1[base]);
    const int i2 = __ldg(&n2[base]);

    const float2 s = __ldg(&feat2[node * 32 + lane]);

    float2 a1 = make_float2(0.f, 0.f);
    float2 a2 = make_float2(0.f, 0.f);

#pragma unroll
    for (int j = 0; j < DEG; j += 4) {
        int x10 = __shfl_sync(0xffffffffu, i1, j + 0);
        int x11 = __shfl_sync(0xffffffffu, i1, j + 1);
        int x12 = __shfl_sync(0xffffffffu, i1, j + 2);
        int x13 = __shfl_sync(0xffffffffu, i1, j + 3);
        int x20 = __shfl_sync(0xffffffffu, i2, j + 0);
        int x21 = __shfl_sync(0xffffffffu, i2, j + 1);
        int x22 = __shfl_sync(0xffffffffu, i2, j + 2);
        int x23 = __shfl_sync(0xffffffffu, i2, j + 3);

        float2 v10 = __ldg(&feat2[x10 * 32 + lane]);
        float2 v11 = __ldg(&feat2[x11 * 32 + lane]);
        float2 v12 = __ldg(&feat2[x12 * 32 + lane]);
        float2 v13 = __ldg(&feat2[x13 * 32 + lane]);
        float2 v20 = __ldg(&feat2[x20 * 32 + lane]);
        float2 v21 = __ldg(&feat2[x21 * 32 + lane]);
        float2 v22 = __ldg(&feat2[x22 * 32 + lane]);
        float2 v23 = __ldg(&feat2[x23 * 32 + lane]);

        a1.x += v10.x + v11.x + v12.x + v13.x;
        a1.y += v10.y + v11.y + v12.y + v13.y;
        a2.x += v20.x + v21.x + v22.x + v23.x;
        a2.y += v20.y + v21.y + v22.y + v23.y;
    }

    // --- wait for relation-3 DMA (phase 0) ---
    asm volatile(
        "{\n\t"
        ".reg .pred P;\n\t"
        "WAIT_%=:\n\t"
        "mbarrier.try_wait.parity.acquire.cta.shared::cta.b64 P, [%0], 0, 0x989680;\n\t"
        "@P bra.uni DONE_%=;\n\t"
        "bra.uni WAIT_%=;\n\t"
        "DONE_%=:\n\t"
        "}" :: "r"(mb) : "memory");

    // --- reduce relation 3 from SMEM (lane owns dims {2l,2l+1}) ---
    float2 a3 = make_float2(0.f, 0.f);
    {
        const float2* rp = reinterpret_cast<const float2*>(&rows[wid][0]) + lane;
#pragma unroll
        for (int j = 0; j < DEG; j++) {
            const float2 v = rp[j * 32];
            a3.x += v.x; a3.y += v.y;
        }
    }

    // --- per-dim softmax weights, agg half only (alpha rows 64+2l, 65+2l) ---
    const int r0 = (ED + 2 * lane) * 3;
    float w00 = __ldg(&alpha[r0 + 0]), w01 = __ldg(&alpha[r0 + 1]), w02 = __ldg(&alpha[r0 + 2]);
    float w10 = __ldg(&alpha[r0 + 3]), w11 = __ldg(&alpha[r0 + 4]), w12 = __ldg(&alpha[r0 + 5]);
    softmax3(w00, w01, w02);
    softmax3(w10, w11, w12);

    const float inv = 1.0f / (float)DEG;
    const float g1x = fmaxf(a1.x * inv, 0.f), g1y = fmaxf(a1.y * inv, 0.f);
    const float g2x = fmaxf(a2.x * inv, 0.f), g2y = fmaxf(a2.y * inv, 0.f);
    const float g3x = fmaxf(a3.x * inv, 0.f), g3y = fmaxf(a3.y * inv, 0.f);

    const float ox = g1x * w00 + g2x * w01 + g3x * w02;
    const float oy = g1y * w10 + g2y * w11 + g3y * w12;

    // --- write 192 floats: [self | relu(self) | weighted agg] ---
    float* ob = out + (size_t)w * 192;
    reinterpret_cast<float2*>(ob)[lane]       = s;
    reinterpret_cast<float2*>(ob + 64)[lane]  = make_float2(fmaxf(s.x, 0.f), fmaxf(s.y, 0.f));
    reinterpret_cast<float2*>(ob + 128)[lane] = make_float2(ox, oy);
}

extern "C" void kernel_launch(void* const* d_in, const int* in_sizes, int n_in,
                              void* d_out, int out_size) {
    const float*  feat  = (const float*)d_in[0];
    const float2* feat2 = (const float2*)d_in[0];
    const float*  alpha = (const float*)d_in[1];
    const int*    nodes = (const int*)d_in[2];
    const int*    n1    = (const int*)d_in[3];
    const int*    n2    = (const int*)d_in[4];
    const int*    n3    = (const int*)d_in[5];
    float*        out   = (float*)d_out;

    interagg_kernel<<<NB / WPC, 32 * WPC>>>(feat, feat2, alpha, nodes, n1, n2, n3, out);
}

// round 14
// speedup vs baseline: 3.9265x; 1.0801x over previous
#include <cuda_runtime.h>
#include <cuda_bf16.h>

// InterAgg (FRAUDRE inter-relation aggregation), GB300 sm_103a.
//
// out[n] = [ self | relu(self) | sum_r relu(mean_j feat[nidx_r[n,j]]) * softmax(alpha)[64:,r] ]
// (softmax rows sum to 1 => aggregated first half == relu(self) exactly)
//
// R13: R1 core (one warp/node, float2 lanes, fully coalesced 256B row
// gathers — the proven 30.8us / 5.2TB/s configuration) plus L2-pollution
// control on the single-touch streams:
//   - index reads via __ldcs (streaming; don't displace feature lines)
//   - output writes via __stcs (streaming; no write-allocate pollution)
// Rationale: dual-engine R12 proved the 5.2TB/s wall is DRAM-pattern-side;
// the only remaining headroom is the ~11MB gap between measured traffic
// (161MB) and the unique-row floor (150MB), attributable to L2 lines lost
// to output/index streams that would otherwise serve duplicate gathers.

#define NB 8192
#define DEG 32
#define ED 64

__device__ __forceinline__ void softmax3(float& a, float& b, float& c) {
    float m = fmaxf(a, fmaxf(b, c));
    float e0 = __expf(a - m);
    float e1 = __expf(b - m);
    float e2 = __expf(c - m);
    float inv = __frcp_rn(e0 + e1 + e2);
    a = e0 * inv; b = e1 * inv; c = e2 * inv;
}

__global__ __launch_bounds__(256, 8)
void interagg_kernel(const float2* __restrict__ feat2,   // features as float2[NUM_NODES*32]
                     const float*  __restrict__ alpha,   // (128, 3)
                     const int*    __restrict__ nodes,   // (NB,)
                     const int*    __restrict__ n1,      // (NB, DEG)
                     const int*    __restrict__ n2,
                     const int*    __restrict__ n3,
                     float*        __restrict__ out)     // (NB, 192)
{
    const int w    = (blockIdx.x * blockDim.x + threadIdx.x) >> 5;
    const int lane = threadIdx.x & 31;
    if (w >= NB) return;

    // --- index loads (coalesced, streaming: read-once per iteration) ---
    const int node = __ldcs(&nodes[w]);
    const int base = w * DEG + lane;
    const int i1 = __ldcs(&n1[base]);
    const int i2 = __ldcs(&n2[base]);
    const int i3 = __ldcs(&n3[base]);

    // --- self row gather: lane l reads float2 at dims {2l,2l+1} ---
    const float2 s = __ldg(&feat2[node * 32 + lane]);

    // --- neighbor gathers: 96 coalesced 256B row reads per warp ---
    float2 a1 = make_float2(0.f, 0.f);
    float2 a2 = make_float2(0.f, 0.f);
    float2 a3 = make_float2(0.f, 0.f);

#pragma unroll
    for (int j = 0; j < DEG; j++) {
        const int x1 = __shfl_sync(0xffffffffu, i1, j);
        const int x2 = __shfl_sync(0xffffffffu, i2, j);
        const int x3 = __shfl_sync(0xffffffffu, i3, j);
        const float2 v1 = __ldg(&feat2[x1 * 32 + lane]);
        const float2 v2 = __ldg(&feat2[x2 * 32 + lane]);
        const float2 v3 = __ldg(&feat2[x3 * 32 + lane]);
        a1.x += v1.x; a1.y += v1.y;
        a2.x += v2.x; a2.y += v2.y;
        a3.x += v3.x; a3.y += v3.y;
    }

    // --- per-dim softmax weights, agg half only (alpha rows 64+2l, 65+2l) ---
    const int r0 = (ED + 2 * lane) * 3;
    float w00 = __ldg(&alpha[r0 + 0]), w01 = __ldg(&alpha[r0 + 1]), w02 = __ldg(&alpha[r0 + 2]);
    float w10 = __ldg(&alpha[r0 + 3]), w11 = __ldg(&alpha[r0 + 4]), w12 = __ldg(&alpha[r0 + 5]);
    softmax3(w00, w01, w02);
    softmax3(w10, w11, w12);

    const float inv = 1.0f / (float)DEG;
    const float g1x = fmaxf(a1.x * inv, 0.f), g1y = fmaxf(a1.y * inv, 0.f);
    const float g2x = fmaxf(a2.x * inv, 0.f), g2y = fmaxf(a2.y * inv, 0.f);
    const float g3x = fmaxf(a3.x * inv, 0.f), g3y = fmaxf(a3.y * inv, 0.f);

    const float ox = g1x * w00 + g2x * w01 + g3x * w02;
    const float oy = g1y * w10 + g2y * w11 + g3y * w12;

    // --- write 192 floats: [self | relu(self) | weighted agg], streaming ---
    float* ob = out + (size_t)w * 192;
    __stcs(&reinterpret_cast<float2*>(ob)[lane], s);
    __stcs(&reinterpret_cast<float2*>(ob + 64)[lane],
           make_float2(fmaxf(s.x, 0.f), fmaxf(s.y, 0.f)));
    __stcs(&reinterpret_cast<float2*>(ob + 128)[lane], make_float2(ox, oy));
}

extern "C" void kernel_launch(void* const* d_in, const int* in_sizes, int n_in,
                              void* d_out, int out_size) {
    const float2* feat2 = (const float2*)d_in[0];
    const float*  alpha = (const float*)d_in[1];
    const int*    nodes = (const int*)d_in[2];
    const int*    n1    = (const int*)d_in[3];
    const int*    n2    = (const int*)d_in[4];
    const int*    n3    = (const int*)d_in[5];
    float*        out   = (float*)d_out;

    const int threads = 256;                                // 8 warps = 8 nodes / block
    const int blocks  = (NB * 32 + threads - 1) / threads;  // 1024
    interagg_kernel<<<blocks, threads>>>(feat2, alpha, nodes, n1, n2, n3, out);
}